// round 8
// baseline (speedup 1.0000x reference)
#include <cuda_runtime.h>

// HierSoftmax: per-token Huffman-path NLL. Single-launch version:
// per-block partials + threadfence/ticket grid reduction (deterministic,
// fixed summation order, no float atomics).
//
// Inputs (metadata order):
//   0: hidden     [8,1024,512] f32
//   1: node_emb   [50256,512]  f32
//   2: path_signs [50257,20]   f32
//   3: targets    [8,1024]     i32
//   4: path_nodes [50257,20]   i32
//   5: path_lens  [50257]      i32
// Output: scalar f32

#define D_DIM     512
#define MAX_DEPTH 20
#define N_TOK     (8 * 1024)

__device__ float g_partials[N_TOK];
__device__ unsigned int g_ticket = 0;   // reset by last block each call

// (128, 6): ~85 regs/thread available -> the ~60-value live set of the
// software-pipelined loop fits with headroom; no spills. 24 warps/SM is
// ample concurrency for a DRAM-bound gather kernel.
__global__ __launch_bounds__(128, 6)
void hs_main_kernel(const float* __restrict__ hidden,
                    const float* __restrict__ node_emb,
                    const float* __restrict__ path_signs,
                    const int*   __restrict__ targets,
                    const int*   __restrict__ path_nodes,
                    const int*   __restrict__ path_lens,
                    float*       __restrict__ out)
{
    const int tok  = blockIdx.x;
    const int tid  = threadIdx.x;
    const int warp = tid >> 5;
    const int lane = tid & 31;

    const int t = __ldg(&targets[tok]);
    int len = __ldg(&path_lens[t]);
    if (len < 1) len = 1;                 // reference: max(path_lens, 1)

    // Hidden row, register-resident (4 float4 per lane, coalesced).
    const float4* h4 = reinterpret_cast<const float4*>(hidden + (size_t)tok * D_DIM);
    const float4 h0 = h4[lane];
    const float4 h1 = h4[lane + 32];
    const float4 h2 = h4[lane + 64];
    const float4 h3 = h4[lane + 96];

    float local = 0.0f;

    // Warp w handles depths d = w, w+4, ... Software-pipelined: next depth's
    // embedding loads are issued BEFORE the current depth's shuffle reduction.
    int d = warp;
    if (d < len) {
        float ps = __ldg(&path_signs[t * MAX_DEPTH + d]);
        const float4* w4 = reinterpret_cast<const float4*>(
            node_emb + (size_t)__ldg(&path_nodes[t * MAX_DEPTH + d]) * D_DIM);
        float4 w0 = w4[lane];
        float4 w1 = w4[lane + 32];
        float4 w2 = w4[lane + 64];
        float4 w3 = w4[lane + 96];

        while (true) {
            const int  dn   = d + 4;
            const bool more = dn < len;

            // Prefetch next depth (predicated; registers unused when !more).
            float ps_n = 0.0f;
            float4 n0, n1, n2, n3;
            if (more) {
                ps_n = __ldg(&path_signs[t * MAX_DEPTH + dn]);
                const float4* v4 = reinterpret_cast<const float4*>(
                    node_emb + (size_t)__ldg(&path_nodes[t * MAX_DEPTH + dn]) * D_DIM);
                n0 = v4[lane];
                n1 = v4[lane + 32];
                n2 = v4[lane + 64];
                n3 = v4[lane + 96];
            }

            // Current depth: per-lane partial dot.
            float a = h0.x * w0.x;   a = fmaf(h0.y, w0.y, a);
            a = fmaf(h0.z, w0.z, a); a = fmaf(h0.w, w0.w, a);
            float b = h1.x * w1.x;   b = fmaf(h1.y, w1.y, b);
            b = fmaf(h1.z, w1.z, b); b = fmaf(h1.w, w1.w, b);
            float c = h2.x * w2.x;   c = fmaf(h2.y, w2.y, c);
            c = fmaf(h2.z, w2.z, c); c = fmaf(h2.w, w2.w, c);
            float e = h3.x * w3.x;   e = fmaf(h3.y, w3.y, e);
            e = fmaf(h3.z, w3.z, e); e = fmaf(h3.w, w3.w, e);
            float dot = (a + b) + (c + e);

            #pragma unroll
            for (int off = 16; off > 0; off >>= 1)
                dot += __shfl_xor_sync(0xffffffffu, dot, off);

            // -log_sigmoid(sign*dot) = softplus(-sign*dot), sign = (ps>=0 ? +1 : -1)
            const float y  = (ps >= 0.0f) ? -dot : dot;
            local += fmaxf(y, 0.0f) + log1pf(__expf(-fabsf(y)));

            if (!more) break;
            d  = dn;
            ps = ps_n;
            w0 = n0; w1 = n1; w2 = n2; w3 = n3;
        }
    }

    __shared__ float wsum[4];
    if (lane == 0) wsum[warp] = local;
    __syncthreads();

    __shared__ bool is_last;
    if (tid == 0) {
        g_partials[tok] = (wsum[0] + wsum[1]) + (wsum[2] + wsum[3]);
        __threadfence();                          // publish partial before ticket
        unsigned int tkt = atomicInc(&g_ticket, 0xffffffffu);
        is_last = (tkt == (unsigned int)(gridDim.x - 1));
    }
    __syncthreads();

    // Last block performs the grid reduction (fixed order -> deterministic).
    if (is_last) {
        const float4* p4 = reinterpret_cast<const float4*>(g_partials);
        float s = 0.0f;
        #pragma unroll
        for (int i = 0; i < (N_TOK / 4) / 128; i++) {   // 16 float4 per thread
            const float4 v = __ldcg(&p4[tid + i * 128]); // L2 (bypass stale L1)
            s += (v.x + v.y) + (v.z + v.w);
        }
        #pragma unroll
        for (int off = 16; off > 0; off >>= 1)
            s += __shfl_xor_sync(0xffffffffu, s, off);

        __shared__ float fs[4];
        if (lane == 0) fs[warp] = s;
        __syncthreads();
        if (tid == 0) {
            out[0] = ((fs[0] + fs[1]) + (fs[2] + fs[3])) / (float)N_TOK;
            g_ticket = 0;                         // reset for next graph replay
        }
    }
}

extern "C" void kernel_launch(void* const* d_in, const int* in_sizes, int n_in,
                              void* d_out, int out_size)
{
    const float* hidden     = (const float*)d_in[0];
    const float* node_emb   = (const float*)d_in[1];
    const float* path_signs = (const float*)d_in[2];
    const int*   targets    = (const int*)  d_in[3];
    const int*   path_nodes = (const int*)  d_in[4];
    const int*   path_lens  = (const int*)  d_in[5];

    hs_main_kernel<<<N_TOK, 128>>>(hidden, node_emb, path_signs,
                                   targets, path_nodes, path_lens,
                                   (float*)d_out);
}